// round 4
// baseline (speedup 1.0000x reference)
#include <cuda_runtime.h>
#include <math.h>

#define BB 512
#define SS 1024
#define TT 52
#define START_TAG 50
#define END_TAG 51
#define LOG2E 1.4426950408889634f

// ---------------- device scratch (no allocations allowed) ----------------
__device__ float  g_E[TT * TT];      // exp(transitions)
__device__ int    g_len[BB];         // per-sequence lengths
__device__ int    g_isU8;            // mask dtype flag
__device__ double g_final[BB];       // per-seq log partition
__device__ double g_gold[BB];        // per-seq gold path score

// ---------------- packed f32x2 helpers (Blackwell) ----------------
__device__ __forceinline__ unsigned long long f2pack(float lo, float hi) {
    unsigned long long r;
    asm("mov.b64 %0, {%1, %2};" : "=l"(r) : "f"(lo), "f"(hi));
    return r;
}
__device__ __forceinline__ float2 f2unpack(unsigned long long a) {
    float2 r;
    asm("mov.b64 {%0, %1}, %2;" : "=f"(r.x), "=f"(r.y) : "l"(a));
    return r;
}
__device__ __forceinline__ float f2lo(unsigned long long a) {
    float r;
    asm("{ .reg .b32 hi; mov.b64 {%0, hi}, %1; }" : "=f"(r) : "l"(a));
    return r;
}
__device__ __forceinline__ unsigned long long f2fma(unsigned long long a,
                                                    unsigned long long b,
                                                    unsigned long long c) {
    unsigned long long d;
    asm("fma.rn.f32x2 %0, %1, %2, %3;" : "=l"(d) : "l"(a), "l"(b), "l"(c));
    return d;
}
__device__ __forceinline__ unsigned long long f2mul(unsigned long long a,
                                                    unsigned long long b) {
    unsigned long long d;
    asm("mul.rn.f32x2 %0, %1, %2;" : "=l"(d) : "l"(a), "l"(b));
    return d;
}
__device__ __forceinline__ unsigned long long f2add(unsigned long long a,
                                                    unsigned long long b) {
    unsigned long long d;
    asm("add.rn.f32x2 %0, %1, %2;" : "=l"(d) : "l"(a), "l"(b));
    return d;
}
__device__ __forceinline__ float ex2(float x) {
    float y;
    asm("ex2.approx.ftz.f32 %0, %1;" : "=f"(y) : "f"(x));
    return y;
}

// ---------------- mask dtype detection + E table ----------------
// Under any 4-byte 0/1 encoding (int32 bool or float32 0.0/1.0), the byte at
// offset b*SS+1 is always 0. Under uint8/bool it equals mask[b][1], which is
// nonzero for sequences with length >= 2 (exist w.h.p.).
__global__ void k_detect(const void* mask, const float* __restrict__ tr) {
    int tid = threadIdx.x;     // 256
    if (tid < 32) {
        const unsigned char* p = (const unsigned char*)mask;
        int any = 0;
        for (int b = tid; b < BB; b += 32)
            any |= (int)p[(size_t)b * SS + 1];
        #pragma unroll
        for (int o = 16; o; o >>= 1) any |= __shfl_xor_sync(0xffffffffu, any, o);
        if (tid == 0) g_isU8 = (any != 0);
    }
    for (int idx = tid; idx < TT * TT; idx += 256)
        g_E[idx] = expf(tr[idx]);
}

// ---------------- fused length + gold score: one 256-thr CTA per row -----
__global__ void k_lengold(const void* mask,
                          const float* __restrict__ feats,
                          const int* __restrict__ tags,
                          const float* __restrict__ tr) {
    int b    = blockIdx.x;
    int tid  = threadIdx.x;      // 256
    int w    = tid >> 5;
    int lane = tid & 31;
    __shared__ int    slen[8];
    __shared__ double sgold[8];
    __shared__ int    len_sh;

    // ---- length ----
    int cnt = 0;
    if (g_isU8) {
        const unsigned char* p = (const unsigned char*)mask + (size_t)b * SS;
        for (int s = tid; s < SS; s += 256) cnt += (p[s] != 0);
    } else {
        const unsigned int* p = (const unsigned int*)mask + (size_t)b * SS;
        for (int s = tid; s < SS; s += 256) cnt += (p[s] != 0);
    }
    #pragma unroll
    for (int o = 16; o; o >>= 1) cnt += __shfl_xor_sync(0xffffffffu, cnt, o);
    if (lane == 0) slen[w] = cnt;
    __syncthreads();
    if (tid == 0) {
        int L = 0;
        #pragma unroll
        for (int i = 0; i < 8; i++) L += slen[i];
        g_len[b] = L;
        len_sh = L;
    }
    __syncthreads();
    const int len = len_sh;

    // ---- gold segments: warp w owns s in [w*128, min(len, w*128+128)) ----
    const int* tg = tags + (size_t)b * SS;
    const float* fb = feats + (size_t)b * SS * TT;
    int s0 = w << 7;
    int s1 = min(len, s0 + 128);
    double acc = 0.0;
    for (int s = s0 + lane; s < s1; s += 32) {
        int tag  = tg[s];
        int prev = (s == 0) ? START_TAG : tg[s - 1];
        acc += (double)fb[(size_t)s * TT + tag] + (double)tr[prev * TT + tag];
    }
    #pragma unroll
    for (int o = 16; o; o >>= 1) acc += __shfl_xor_sync(0xffffffffu, acc, o);
    if (lane == 0) {
        if (((len - 1) >> 7) == w)   // this segment owns the last step
            acc += (double)tr[tg[len - 1] * TT + END_TAG];
        sgold[w] = acc;
    }
    __syncthreads();
    if (tid == 0) {
        double g = 0.0;
        #pragma unroll
        for (int i = 0; i < 8; i++) g += sgold[i];
        g_gold[b] = g;
    }
}

// ---------------- main forward scan: one 64-thread CTA per sequence -------
// Scaled-linear domain with lazy exact power-of-2 renorm. Chain surgery:
// all 13 LDS.128 batched up front; exp(f) and the renorm scale computed off
// the critical path and folded into one multiplier; one barrier per step.
__global__ void __launch_bounds__(64) k_main(const float* __restrict__ feats,
                                             const float* __restrict__ tr) {
    const int b = blockIdx.x;
    const int j = threadIdx.x;           // 0..63, tags 0..51 active
    const bool act = (j < TT);
    const int jj = act ? j : (TT - 1);   // clamped for safe addressing
    __shared__ __align__(16) float shq[2][64];
    __shared__ float shred[2];

    const int len = g_len[b];
    const float* fb = feats + (size_t)b * SS * TT;

    // E column j packed over i-pairs: Ep[c] = (E[2c][j], E[2c+1][j])
    unsigned long long Ep[26];
    #pragma unroll
    for (int c = 0; c < 26; c++) {
        float e0 = act ? g_E[(2 * c) * TT + j] : 0.0f;
        float e1 = act ? g_E[(2 * c + 1) * TT + j] : 0.0f;
        Ep[c] = f2pack(e0, e1);
    }

    // ---- init: part0 = feats[b,0,:] + trans[START,:] ----
    float p0 = act ? (fb[j] + tr[START_TAG * TT + j]) : -1e30f;
    float m = p0;
    #pragma unroll
    for (int o = 16; o; o >>= 1) m = fmaxf(m, __shfl_xor_sync(0xffffffffu, m, o));
    if ((j & 31) == 0) shred[j >> 5] = m;
    __syncthreads();
    const float m0 = fmaxf(shred[0], shred[1]);
    shq[0][j] = act ? ex2((p0 - m0) * LOG2E) : 0.0f;
    int Ktot = 0;
    __syncthreads();

    // ---- emission prefetch pipeline (distance 4), pre-scaled by log2e ----
    const float* pf = fb + jj;     // row 0 of this thread's column
    float fl0 = (1 < len) ? pf[1 * TT] * LOG2E : 0.0f;
    float fl1 = (2 < len) ? pf[2 * TT] * LOG2E : 0.0f;
    float fl2 = (3 < len) ? pf[3 * TT] * LOG2E : 0.0f;
    float fl3 = (4 < len) ? pf[4 * TT] * LOG2E : 0.0f;
    pf += 5 * TT;

    for (int s = 1; s < len; s++) {
        // off-chain: exp(f) from prefetched value
        float efcur = ex2(fl0);
        fl0 = fl1; fl1 = fl2; fl2 = fl3;
        int sp = s + 4;
        float nf = 0.0f;
        if (sp < len) nf = *pf;
        pf += TT;
        fl3 = nf * LOG2E;

        // batch-load the whole q vector (13 x LDS.128, back-to-back)
        const ulonglong2* q8 = (const ulonglong2*)shq[(s - 1) & 1];
        ulonglong2 qv[13];
        #pragma unroll
        for (int c = 0; c < 13; c++) qv[c] = q8[c];

        // off-chain: renorm scale from q[0]'s exponent (exact power of 2)
        float q0 = f2lo(qv[0].x);
        int ex = ((__float_as_int(q0) >> 23) & 0xFF) - 127;
        Ktot += ex;
        float scale = __int_as_float((127 - ex) << 23);   // exact 2^-ex
        float pre = scale * efcur;

        // matvec: u_j = sum_i q_i * E[i][j], packed 2 i's per FFMA2
        unsigned long long a0 = f2mul(qv[0].x, Ep[0]);
        unsigned long long a1 = f2mul(qv[0].y, Ep[1]);
        unsigned long long a2 = f2mul(qv[1].x, Ep[2]);
        unsigned long long a3 = f2mul(qv[1].y, Ep[3]);
        #pragma unroll
        for (int c = 2; c < 13; c++) {
            a0 = f2fma(qv[c].x, Ep[2 * c],     a0);
            a1 = f2fma(qv[c].y, Ep[2 * c + 1], a1);
            if (c + 1 < 13) { c++;
                a2 = f2fma(qv[c].x, Ep[2 * c],     a2);
                a3 = f2fma(qv[c].y, Ep[2 * c + 1], a3);
            }
        }
        a0 = f2add(a0, a2);
        a1 = f2add(a1, a3);
        a0 = f2add(a0, a1);
        float2 h = f2unpack(a0);
        float u = (h.x + h.y) * pre;

        shq[s & 1][j] = u;          // padded to 64: unconditional store
        __syncthreads();
    }

    // ---- final: part_END = m0 + Ktot*ln2 + log( sum_i q_i * E[i][END] ) --
    const float* rq = shq[(len - 1) & 1];
    float v = act ? rq[j] * g_E[j * TT + END_TAG] : 0.0f;
    #pragma unroll
    for (int o = 16; o; o >>= 1) v += __shfl_xor_sync(0xffffffffu, v, o);
    if ((j & 31) == 0) shred[j >> 5] = v;
    __syncthreads();
    if (j == 0) {
        double dot = (double)shred[0] + (double)shred[1];
        g_final[b] = (double)m0 + (double)Ktot * 0.6931471805599453 + log(dot);
    }
}

// ---------------- final reduction: NLL = sum(final) - sum(gold) ----------
__global__ void k_reduce(float* out) {
    __shared__ double sh[16];
    int tid = threadIdx.x;  // 512 threads
    double a = g_final[tid] - g_gold[tid];
    #pragma unroll
    for (int o = 16; o; o >>= 1) a += __shfl_xor_sync(0xffffffffu, a, o);
    if ((tid & 31) == 0) sh[tid >> 5] = a;
    __syncthreads();
    if (tid < 32) {
        double b = (tid < 16) ? sh[tid] : 0.0;
        #pragma unroll
        for (int o = 8; o; o >>= 1) b += __shfl_xor_sync(0xffffffffu, b, o);
        if (tid == 0) out[0] = (float)b;
    }
}

// ---------------- launch ----------------
extern "C" void kernel_launch(void* const* d_in, const int* in_sizes, int n_in,
                              void* d_out, int out_size) {
    const float* feats = (const float*)d_in[0];
    const void*  mask  = d_in[1];
    const int*   tags  = (const int*)d_in[2];
    const float* tr    = (const float*)d_in[3];
    float* out = (float*)d_out;

    k_detect<<<1, 256>>>(mask, tr);               // dtype flag + E table
    k_lengold<<<BB, 256>>>(mask, feats, tags, tr);
    k_main<<<BB, 64>>>(feats, tr);
    k_reduce<<<1, 512>>>(out);
}

// round 5
// speedup vs baseline: 5.1197x; 5.1197x over previous
#include <cuda_runtime.h>
#include <math.h>

#define BB 512
#define SS 1024
#define TT 52
#define START_TAG 50
#define END_TAG 51
#define LOG2E 1.4426950408889634f

// ---------------- device scratch (no allocations allowed) ----------------
__device__ float  g_E[TT * TT];      // exp(transitions)
__device__ int    g_len[BB];         // per-sequence lengths
__device__ int    g_isU8;            // mask dtype flag
__device__ double g_final[BB];       // per-seq log partition
__device__ double g_gold[BB];        // per-seq gold path score

// ---------------- packed f32x2 helpers (Blackwell) ----------------
__device__ __forceinline__ unsigned long long f2pack(float lo, float hi) {
    unsigned long long r;
    asm("mov.b64 %0, {%1, %2};" : "=l"(r) : "f"(lo), "f"(hi));
    return r;
}
__device__ __forceinline__ float2 f2unpack(unsigned long long a) {
    float2 r;
    asm("mov.b64 {%0, %1}, %2;" : "=f"(r.x), "=f"(r.y) : "l"(a));
    return r;
}
__device__ __forceinline__ float f2lo(unsigned long long a) {
    float r;
    asm("{ .reg .b32 hi; mov.b64 {%0, hi}, %1; }" : "=f"(r) : "l"(a));
    return r;
}
__device__ __forceinline__ unsigned long long f2fma(unsigned long long a,
                                                    unsigned long long b,
                                                    unsigned long long c) {
    unsigned long long d;
    asm("fma.rn.f32x2 %0, %1, %2, %3;" : "=l"(d) : "l"(a), "l"(b), "l"(c));
    return d;
}
__device__ __forceinline__ unsigned long long f2mul(unsigned long long a,
                                                    unsigned long long b) {
    unsigned long long d;
    asm("mul.rn.f32x2 %0, %1, %2;" : "=l"(d) : "l"(a), "l"(b));
    return d;
}
__device__ __forceinline__ unsigned long long f2add(unsigned long long a,
                                                    unsigned long long b) {
    unsigned long long d;
    asm("add.rn.f32x2 %0, %1, %2;" : "=l"(d) : "l"(a), "l"(b));
    return d;
}
__device__ __forceinline__ float ex2(float x) {
    float y;
    asm("ex2.approx.ftz.f32 %0, %1;" : "=f"(y) : "f"(x));
    return y;
}

// ---------------- mask dtype detection + E table ----------------
// Under any 4-byte 0/1 encoding (int32 bool or float32 0.0/1.0), the byte at
// offset b*SS+1 is always 0. Under uint8/bool it equals mask[b][1], which is
// nonzero for sequences with length >= 2 (exist w.h.p.).
__global__ void k_detect(const void* mask, const float* __restrict__ tr) {
    int tid = threadIdx.x;     // 256
    if (tid < 32) {
        const unsigned char* p = (const unsigned char*)mask;
        int any = 0;
        for (int b = tid; b < BB; b += 32)
            any |= (int)p[(size_t)b * SS + 1];
        #pragma unroll
        for (int o = 16; o; o >>= 1) any |= __shfl_xor_sync(0xffffffffu, any, o);
        if (tid == 0) g_isU8 = (any != 0);
    }
    for (int idx = tid; idx < TT * TT; idx += 256)
        g_E[idx] = expf(tr[idx]);
}

// ---------------- fused length + gold score: one 256-thr CTA per row -----
__global__ void k_lengold(const void* mask,
                          const float* __restrict__ feats,
                          const int* __restrict__ tags,
                          const float* __restrict__ tr) {
    int b    = blockIdx.x;
    int tid  = threadIdx.x;      // 256
    int w    = tid >> 5;
    int lane = tid & 31;
    __shared__ int    slen[8];
    __shared__ double sgold[8];
    __shared__ int    len_sh;

    // ---- length ----
    int cnt = 0;
    if (g_isU8) {
        const unsigned char* p = (const unsigned char*)mask + (size_t)b * SS;
        for (int s = tid; s < SS; s += 256) cnt += (p[s] != 0);
    } else {
        const unsigned int* p = (const unsigned int*)mask + (size_t)b * SS;
        for (int s = tid; s < SS; s += 256) cnt += (p[s] != 0);
    }
    #pragma unroll
    for (int o = 16; o; o >>= 1) cnt += __shfl_xor_sync(0xffffffffu, cnt, o);
    if (lane == 0) slen[w] = cnt;
    __syncthreads();
    if (tid == 0) {
        int L = 0;
        #pragma unroll
        for (int i = 0; i < 8; i++) L += slen[i];
        g_len[b] = L;
        len_sh = L;
    }
    __syncthreads();
    const int len = len_sh;

    // ---- gold segments: warp w owns s in [w*128, min(len, w*128+128)) ----
    const int* tg = tags + (size_t)b * SS;
    const float* fb = feats + (size_t)b * SS * TT;
    int s0 = w << 7;
    int s1 = min(len, s0 + 128);
    double acc = 0.0;
    for (int s = s0 + lane; s < s1; s += 32) {
        int tag  = tg[s];
        int prev = (s == 0) ? START_TAG : tg[s - 1];
        acc += (double)fb[(size_t)s * TT + tag] + (double)tr[prev * TT + tag];
    }
    #pragma unroll
    for (int o = 16; o; o >>= 1) acc += __shfl_xor_sync(0xffffffffu, acc, o);
    if (lane == 0) {
        if (((len - 1) >> 7) == w)   // this segment owns the last step
            acc += (double)tr[tg[len - 1] * TT + END_TAG];
        sgold[w] = acc;
    }
    __syncthreads();
    if (tid == 0) {
        double g = 0.0;
        #pragma unroll
        for (int i = 0; i < 8; i++) g += sgold[i];
        g_gold[b] = g;
    }
}

// ---------------- main forward scan: one 64-thread CTA per sequence -------
// Scaled-linear domain with lazy exact power-of-2 renorm. All 13 LDS.128
// batched up front; exp(f) and the renorm scale computed off the critical
// path and folded into one multiplier; one barrier per step. Accumulation
// loop uses only compile-time-resolvable control flow (full unroll — the
// round-4 regression was a mutated induction variable demoting qv/Ep to
// local memory).
__global__ void __launch_bounds__(64) k_main(const float* __restrict__ feats,
                                             const float* __restrict__ tr) {
    const int b = blockIdx.x;
    const int j = threadIdx.x;           // 0..63, tags 0..51 active
    const bool act = (j < TT);
    const int jj = act ? j : (TT - 1);   // clamped for safe addressing
    __shared__ __align__(16) float shq[2][64];
    __shared__ float shred[2];

    const int len = g_len[b];
    const float* fb = feats + (size_t)b * SS * TT;

    // E column j packed over i-pairs: Ep[c] = (E[2c][j], E[2c+1][j])
    unsigned long long Ep[26];
    #pragma unroll
    for (int c = 0; c < 26; c++) {
        float e0 = act ? g_E[(2 * c) * TT + j] : 0.0f;
        float e1 = act ? g_E[(2 * c + 1) * TT + j] : 0.0f;
        Ep[c] = f2pack(e0, e1);
    }

    // ---- init: part0 = feats[b,0,:] + trans[START,:] ----
    float p0 = act ? (fb[j] + tr[START_TAG * TT + j]) : -1e30f;
    float m = p0;
    #pragma unroll
    for (int o = 16; o; o >>= 1) m = fmaxf(m, __shfl_xor_sync(0xffffffffu, m, o));
    if ((j & 31) == 0) shred[j >> 5] = m;
    __syncthreads();
    const float m0 = fmaxf(shred[0], shred[1]);
    shq[0][j] = act ? ex2((p0 - m0) * LOG2E) : 0.0f;
    int Ktot = 0;
    __syncthreads();

    // ---- emission prefetch pipeline (distance 4), pre-scaled by log2e ----
    const float* pf = fb + jj;     // this thread's column
    float fl0 = (1 < len) ? pf[1 * TT] * LOG2E : 0.0f;
    float fl1 = (2 < len) ? pf[2 * TT] * LOG2E : 0.0f;
    float fl2 = (3 < len) ? pf[3 * TT] * LOG2E : 0.0f;
    float fl3 = (4 < len) ? pf[4 * TT] * LOG2E : 0.0f;
    pf += 5 * TT;

    for (int s = 1; s < len; s++) {
        // off-chain: exp(f) from prefetched value
        float efcur = ex2(fl0);
        fl0 = fl1; fl1 = fl2; fl2 = fl3;
        int sp = s + 4;
        float nf = 0.0f;
        if (sp < len) nf = *pf;
        pf += TT;
        fl3 = nf * LOG2E;

        // batch-load the whole q vector (13 x LDS.128, back-to-back)
        const ulonglong2* q8 = (const ulonglong2*)shq[(s - 1) & 1];
        ulonglong2 qv[13];
        #pragma unroll
        for (int c = 0; c < 13; c++) qv[c] = q8[c];

        // off-chain: renorm scale from q[0]'s exponent (exact power of 2)
        float q0 = f2lo(qv[0].x);
        int ex = ((__float_as_int(q0) >> 23) & 0xFF) - 127;
        Ktot += ex;
        float scale = __int_as_float((127 - ex) << 23);   // exact 2^-ex
        float pre = scale * efcur;

        // matvec: u_j = sum_i q_i * E[i][j], packed 2 i's per FFMA2.
        // 4 accumulators; (c & 1) resolves at compile time under unroll.
        unsigned long long a0 = f2mul(qv[0].x, Ep[0]);
        unsigned long long a1 = f2mul(qv[0].y, Ep[1]);
        unsigned long long a2 = f2mul(qv[1].x, Ep[2]);
        unsigned long long a3 = f2mul(qv[1].y, Ep[3]);
        #pragma unroll
        for (int c = 2; c < 13; c++) {
            if (c & 1) {
                a2 = f2fma(qv[c].x, Ep[2 * c],     a2);
                a3 = f2fma(qv[c].y, Ep[2 * c + 1], a3);
            } else {
                a0 = f2fma(qv[c].x, Ep[2 * c],     a0);
                a1 = f2fma(qv[c].y, Ep[2 * c + 1], a1);
            }
        }
        a0 = f2add(a0, a2);
        a1 = f2add(a1, a3);
        a0 = f2add(a0, a1);
        float2 h = f2unpack(a0);
        float u = (h.x + h.y) * pre;

        shq[s & 1][j] = u;          // padded to 64: unconditional store
        __syncthreads();
    }

    // ---- final: part_END = m0 + Ktot*ln2 + log( sum_i q_i * E[i][END] ) --
    const float* rq = shq[(len - 1) & 1];
    float v = act ? rq[j] * g_E[j * TT + END_TAG] : 0.0f;
    #pragma unroll
    for (int o = 16; o; o >>= 1) v += __shfl_xor_sync(0xffffffffu, v, o);
    if ((j & 31) == 0) shred[j >> 5] = v;
    __syncthreads();
    if (j == 0) {
        double dot = (double)shred[0] + (double)shred[1];
        g_final[b] = (double)m0 + (double)Ktot * 0.6931471805599453 + log(dot);
    }
}

// ---------------- final reduction: NLL = sum(final) - sum(gold) ----------
__global__ void k_reduce(float* out) {
    __shared__ double sh[16];
    int tid = threadIdx.x;  // 512 threads
    double a = g_final[tid] - g_gold[tid];
    #pragma unroll
    for (int o = 16; o; o >>= 1) a += __shfl_xor_sync(0xffffffffu, a, o);
    if ((tid & 31) == 0) sh[tid >> 5] = a;
    __syncthreads();
    if (tid < 32) {
        double b = (tid < 16) ? sh[tid] : 0.0;
        #pragma unroll
        for (int o = 8; o; o >>= 1) b += __shfl_xor_sync(0xffffffffu, b, o);
        if (tid == 0) out[0] = (float)b;
    }
}

// ---------------- launch ----------------
extern "C" void kernel_launch(void* const* d_in, const int* in_sizes, int n_in,
                              void* d_out, int out_size) {
    const float* feats = (const float*)d_in[0];
    const void*  mask  = d_in[1];
    const int*   tags  = (const int*)d_in[2];
    const float* tr    = (const float*)d_in[3];
    float* out = (float*)d_out;

    k_detect<<<1, 256>>>(mask, tr);               // dtype flag + E table
    k_lengold<<<BB, 256>>>(mask, feats, tags, tr);
    k_main<<<BB, 64>>>(feats, tr);
    k_reduce<<<1, 512>>>(out);
}

// round 6
// speedup vs baseline: 6.8973x; 1.3472x over previous
#include <cuda_runtime.h>
#include <math.h>

#define BB 512
#define SS 1024
#define TT 52
#define START_TAG 50
#define END_TAG 51
#define LOG2E 1.4426950408889634f
#define LN2 0.6931471805599453

// ---------------- device scratch (no allocations allowed) ----------------
__device__ __align__(16) float g_E[TT * TT];   // exp(transitions)
__device__ int    g_len[BB];
__device__ int    g_isU8;
__device__ float  g_alpha[BB][64];   // scaled forward vector at meet point
__device__ float  g_beta[BB][64];    // scaled backward vector at meet point
__device__ int    g_Ka[BB], g_Kb[BB];
__device__ float  g_m0[BB];
__device__ double g_gold[BB];
__device__ double g_final[BB];

// ---------------- packed f32x2 helpers (Blackwell) ----------------
__device__ __forceinline__ unsigned long long f2pack(float lo, float hi) {
    unsigned long long r;
    asm("mov.b64 %0, {%1, %2};" : "=l"(r) : "f"(lo), "f"(hi));
    return r;
}
__device__ __forceinline__ float2 f2unpack(unsigned long long a) {
    float2 r;
    asm("mov.b64 {%0, %1}, %2;" : "=f"(r.x), "=f"(r.y) : "l"(a));
    return r;
}
__device__ __forceinline__ float f2lo(unsigned long long a) {
    float r;
    asm("{ .reg .b32 hi; mov.b64 {%0, hi}, %1; }" : "=f"(r) : "l"(a));
    return r;
}
__device__ __forceinline__ unsigned long long f2fma(unsigned long long a,
                                                    unsigned long long b,
                                                    unsigned long long c) {
    unsigned long long d;
    asm("fma.rn.f32x2 %0, %1, %2, %3;" : "=l"(d) : "l"(a), "l"(b), "l"(c));
    return d;
}
__device__ __forceinline__ unsigned long long f2mul(unsigned long long a,
                                                    unsigned long long b) {
    unsigned long long d;
    asm("mul.rn.f32x2 %0, %1, %2;" : "=l"(d) : "l"(a), "l"(b));
    return d;
}
__device__ __forceinline__ unsigned long long f2add(unsigned long long a,
                                                    unsigned long long b) {
    unsigned long long d;
    asm("add.rn.f32x2 %0, %1, %2;" : "=l"(d) : "l"(a), "l"(b));
    return d;
}
__device__ __forceinline__ float ex2(float x) {
    float y;
    asm("ex2.approx.ftz.f32 %0, %1;" : "=f"(y) : "f"(x));
    return y;
}

// shared matvec: u_j = sum over 26 packed pairs, 4 accumulators
__device__ __forceinline__ float matvec26(const ulonglong2* qv,
                                          const unsigned long long* Ep) {
    unsigned long long a0 = f2mul(qv[0].x, Ep[0]);
    unsigned long long a1 = f2mul(qv[0].y, Ep[1]);
    unsigned long long a2 = f2mul(qv[1].x, Ep[2]);
    unsigned long long a3 = f2mul(qv[1].y, Ep[3]);
    #pragma unroll
    for (int c = 2; c < 13; c++) {
        if (c & 1) {
            a2 = f2fma(qv[c].x, Ep[2 * c],     a2);
            a3 = f2fma(qv[c].y, Ep[2 * c + 1], a3);
        } else {
            a0 = f2fma(qv[c].x, Ep[2 * c],     a0);
            a1 = f2fma(qv[c].y, Ep[2 * c + 1], a1);
        }
    }
    a0 = f2add(a0, a2);
    a1 = f2add(a1, a3);
    a0 = f2add(a0, a1);
    float2 h = f2unpack(a0);
    return h.x + h.y;
}

// ---------------- mask dtype detection + E table ----------------
__global__ void k_detect(const void* mask, const float* __restrict__ tr) {
    int tid = threadIdx.x;     // 256
    if (tid < 32) {
        const unsigned char* p = (const unsigned char*)mask;
        int any = 0;
        for (int b = tid; b < BB; b += 32)
            any |= (int)p[(size_t)b * SS + 1];
        #pragma unroll
        for (int o = 16; o; o >>= 1) any |= __shfl_xor_sync(0xffffffffu, any, o);
        if (tid == 0) g_isU8 = (any != 0);
    }
    for (int idx = tid; idx < TT * TT; idx += 256)
        g_E[idx] = expf(tr[idx]);
}

// ---------------- fused length + gold score: one 256-thr CTA per row -----
__global__ void k_lengold(const void* mask,
                          const float* __restrict__ feats,
                          const int* __restrict__ tags,
                          const float* __restrict__ tr) {
    int b    = blockIdx.x;
    int tid  = threadIdx.x;      // 256
    int w    = tid >> 5;
    int lane = tid & 31;
    __shared__ int    slen[8];
    __shared__ double sgold[8];
    __shared__ int    len_sh;

    int cnt = 0;
    if (g_isU8) {
        const unsigned char* p = (const unsigned char*)mask + (size_t)b * SS;
        for (int s = tid; s < SS; s += 256) cnt += (p[s] != 0);
    } else {
        const unsigned int* p = (const unsigned int*)mask + (size_t)b * SS;
        for (int s = tid; s < SS; s += 256) cnt += (p[s] != 0);
    }
    #pragma unroll
    for (int o = 16; o; o >>= 1) cnt += __shfl_xor_sync(0xffffffffu, cnt, o);
    if (lane == 0) slen[w] = cnt;
    __syncthreads();
    if (tid == 0) {
        int L = 0;
        #pragma unroll
        for (int i = 0; i < 8; i++) L += slen[i];
        g_len[b] = L;
        len_sh = L;
    }
    __syncthreads();
    const int len = len_sh;

    const int* tg = tags + (size_t)b * SS;
    const float* fb = feats + (size_t)b * SS * TT;
    int s0 = w << 7;
    int s1 = min(len, s0 + 128);
    double acc = 0.0;
    for (int s = s0 + lane; s < s1; s += 32) {
        int tag  = tg[s];
        int prev = (s == 0) ? START_TAG : tg[s - 1];
        acc += (double)fb[(size_t)s * TT + tag] + (double)tr[prev * TT + tag];
    }
    #pragma unroll
    for (int o = 16; o; o >>= 1) acc += __shfl_xor_sync(0xffffffffu, acc, o);
    if (lane == 0) {
        if (((len - 1) >> 7) == w)
            acc += (double)tr[tg[len - 1] * TT + END_TAG];
        sgold[w] = acc;
    }
    __syncthreads();
    if (tid == 0) {
        double g = 0.0;
        #pragma unroll
        for (int i = 0; i < 8; i++) g += sgold[i];
        g_gold[b] = g;
    }
}

// ---------------- forward/backward scan, meet in the middle ---------------
// CTA 0..511: forward alpha over s=0..m; CTA 512..1023: backward beta over
// s=len-1..m, m=(len-1)/2. Halves the serial chain and doubles resident
// warps. Per-step machinery identical to round 3 (batched LDS, off-chain
// ex2+renorm, one barrier).
__global__ void __launch_bounds__(64) k_main(const float* __restrict__ feats,
                                             const float* __restrict__ tr) {
    const int cta = blockIdx.x;
    const int b = cta & (BB - 1);
    const bool isFwd = cta < BB;
    const int j = threadIdx.x;           // 0..63, tags 0..51 active
    const bool act = (j < TT);
    const int jj = act ? j : (TT - 1);
    __shared__ __align__(16) float shq[2][64];
    __shared__ float shred[2];

    const int len = g_len[b];
    const int m = (len - 1) >> 1;
    const float* fb = feats + (size_t)b * SS * TT;

    if (isFwd) {
        const int L = m + 1;             // effective length: steps s=1..m
        // E column j packed over i-pairs
        unsigned long long Ep[26];
        #pragma unroll
        for (int c = 0; c < 26; c++) {
            float e0 = act ? g_E[(2 * c) * TT + j] : 0.0f;
            float e1 = act ? g_E[(2 * c + 1) * TT + j] : 0.0f;
            Ep[c] = f2pack(e0, e1);
        }

        float p0 = act ? (fb[j] + tr[START_TAG * TT + j]) : -1e30f;
        float mx = p0;
        #pragma unroll
        for (int o = 16; o; o >>= 1) mx = fmaxf(mx, __shfl_xor_sync(0xffffffffu, mx, o));
        if ((j & 31) == 0) shred[j >> 5] = mx;
        __syncthreads();
        const float m0 = fmaxf(shred[0], shred[1]);
        float last = act ? ex2((p0 - m0) * LOG2E) : 0.0f;
        shq[0][j] = last;
        int Ktot = 0;
        __syncthreads();

        const float* pf = fb + jj;
        float fl0 = (1 < L) ? pf[1 * TT] * LOG2E : 0.0f;
        float fl1 = (2 < L) ? pf[2 * TT] * LOG2E : 0.0f;
        float fl2 = (3 < L) ? pf[3 * TT] * LOG2E : 0.0f;
        float fl3 = (4 < L) ? pf[4 * TT] * LOG2E : 0.0f;
        pf += 5 * TT;

        for (int s = 1; s < L; s++) {
            float efcur = ex2(fl0);
            fl0 = fl1; fl1 = fl2; fl2 = fl3;
            int sp = s + 4;
            float nf = 0.0f;
            if (sp < L) nf = *pf;
            pf += TT;
            fl3 = nf * LOG2E;

            const ulonglong2* q8 = (const ulonglong2*)shq[(s - 1) & 1];
            ulonglong2 qv[13];
            #pragma unroll
            for (int c = 0; c < 13; c++) qv[c] = q8[c];

            float q0 = f2lo(qv[0].x);
            int ex = ((__float_as_int(q0) >> 23) & 0xFF) - 127;
            Ktot += ex;
            float scale = __int_as_float((127 - ex) << 23);
            float pre = scale * efcur;

            float u = matvec26(qv, Ep) * pre;
            last = u;
            shq[s & 1][j] = u;
            __syncthreads();
        }
        g_alpha[b][j] = last;
        if (j == 0) { g_Ka[b] = Ktot; g_m0[b] = m0; }
    } else {
        const int N = len - 1 - m;       // iterations: s = len-2 .. m
        // E row jj packed over j-pairs (contiguous -> direct 8B loads)
        unsigned long long Ep[26];
        const unsigned long long* Erow =
            (const unsigned long long*)(g_E + jj * TT);
        #pragma unroll
        for (int c = 0; c < 26; c++) Ep[c] = act ? Erow[c] : 0ull;

        float Eend = act ? g_E[jj * TT + END_TAG] : 0.0f;
        float last;
        if (len >= 2) {
            float fl = act ? fb[(size_t)(len - 1) * TT + j] : 0.0f;
            last = act ? ex2(fl * LOG2E) * Eend : 0.0f;
        } else {
            last = act ? Eend : 0.0f;    // len==1: beta_0 = E[:,END], no ef
        }
        shq[0][j] = last;
        int Ktot = 0;
        __syncthreads();

        // emission f_s needed only for s > m  <=>  iteration k <= N-2
        const float* pb = fb + jj;
        float fl0 = (N >= 2) ? pb[(size_t)(len - 2) * TT] * LOG2E : 0.0f;
        float fl1 = (N >= 3) ? pb[(size_t)(len - 3) * TT] * LOG2E : 0.0f;
        float fl2 = (N >= 4) ? pb[(size_t)(len - 4) * TT] * LOG2E : 0.0f;
        float fl3 = (N >= 5) ? pb[(size_t)(len - 5) * TT] * LOG2E : 0.0f;

        for (int k = 0; k < N; k++) {
            float efcur = ex2(fl0);      // == 1.0 on the final (s==m) step
            fl0 = fl1; fl1 = fl2; fl2 = fl3;
            int kk = k + 4;
            float nf = 0.0f;
            if (kk <= N - 2) nf = pb[(size_t)(len - 2 - kk) * TT];
            fl3 = nf * LOG2E;

            const ulonglong2* q8 = (const ulonglong2*)shq[k & 1];
            ulonglong2 qv[13];
            #pragma unroll
            for (int c = 0; c < 13; c++) qv[c] = q8[c];

            float q0 = f2lo(qv[0].x);
            int ex = ((__float_as_int(q0) >> 23) & 0xFF) - 127;
            Ktot += ex;
            float scale = __int_as_float((127 - ex) << 23);
            float pre = scale * efcur;

            float u = matvec26(qv, Ep) * pre;
            last = u;
            shq[(k + 1) & 1][j] = u;
            __syncthreads();
        }
        g_beta[b][j] = last;
        if (j == 0) g_Kb[b] = Ktot;
    }
}

// ---------------- combine: logZ_b - gold_b ----------------
__global__ void k_combine() {
    int b = blockIdx.x;
    int l = threadIdx.x;   // 32
    double d = (double)g_alpha[b][l] * (double)g_beta[b][l];
    if (l < TT - 32)
        d += (double)g_alpha[b][l + 32] * (double)g_beta[b][l + 32];
    #pragma unroll
    for (int o = 16; o; o >>= 1) d += __shfl_xor_sync(0xffffffffu, d, o);
    if (l == 0) {
        double logZ = (double)g_m0[b] +
                      (double)(g_Ka[b] + g_Kb[b]) * LN2 + log(d);
        g_final[b] = logZ - g_gold[b];
    }
}

// ---------------- final reduction ----------------
__global__ void k_reduce(float* out) {
    __shared__ double sh[16];
    int tid = threadIdx.x;  // 512 threads
    double a = g_final[tid];
    #pragma unroll
    for (int o = 16; o; o >>= 1) a += __shfl_xor_sync(0xffffffffu, a, o);
    if ((tid & 31) == 0) sh[tid >> 5] = a;
    __syncthreads();
    if (tid < 32) {
        double v = (tid < 16) ? sh[tid] : 0.0;
        #pragma unroll
        for (int o = 8; o; o >>= 1) v += __shfl_xor_sync(0xffffffffu, v, o);
        if (tid == 0) out[0] = (float)v;
    }
}

// ---------------- launch ----------------
extern "C" void kernel_launch(void* const* d_in, const int* in_sizes, int n_in,
                              void* d_out, int out_size) {
    const float* feats = (const float*)d_in[0];
    const void*  mask  = d_in[1];
    const int*   tags  = (const int*)d_in[2];
    const float* tr    = (const float*)d_in[3];
    float* out = (float*)d_out;

    k_detect<<<1, 256>>>(mask, tr);
    k_lengold<<<BB, 256>>>(mask, feats, tags, tr);
    k_main<<<2 * BB, 64>>>(feats, tr);
    k_combine<<<BB, 32>>>();
    k_reduce<<<1, 512>>>(out);
}